// round 15
// baseline (speedup 1.0000x reference)
#include <cuda_runtime.h>
#include <math.h>

#define BB 8
#define NN 4096
#define WW 64
#define RR 4
#define EPSC 1e-8f

typedef unsigned long long u64;

// ---- f32x2 packed helpers (sm_103a) -----------------------------------------
__device__ __forceinline__ u64 pack2(float lo, float hi) {
    u64 r; asm("mov.b64 %0, {%1, %2};" : "=l"(r) : "f"(lo), "f"(hi)); return r;
}
__device__ __forceinline__ void unpack2(float& lo, float& hi, u64 v) {
    asm("mov.b64 {%0, %1}, %2;" : "=f"(lo), "=f"(hi) : "l"(v));
}
__device__ __forceinline__ u64 fma2(u64 a, u64 b, u64 c) {
    u64 d; asm("fma.rn.f32x2 %0, %1, %2, %3;" : "=l"(d) : "l"(a), "l"(b), "l"(c)); return d;
}
__device__ __forceinline__ u64 add2(u64 a, u64 b) {
    u64 d; asm("add.rn.f32x2 %0, %1, %2;" : "=l"(d) : "l"(a), "l"(b)); return d;
}
__device__ __forceinline__ u64 mul2(u64 a, u64 b) {
    u64 d; asm("mul.rn.f32x2 %0, %1, %2;" : "=l"(d) : "l"(a), "l"(b)); return d;
}

// ---------------- scratch (no allocs allowed -> __device__ globals) ----------
__device__ __align__(16) float g_usage[BB*NN];
__device__ __align__(16) float g_zw[BB*NN];
__device__ __align__(16) float g_alloc[BB*NN];
__device__ __align__(16) float g_ww[BB*NN];
__device__ __align__(16) float g_memnew[BB*NN*WW];
__device__ __align__(16) float g_zr[BB*NN*RR];
__device__ __align__(16) float g_cbr[BB*NN*RR];
__device__ __align__(16) float g_fwd[BB*NN*RR];
__device__ __align__(16) float g_bwd[BB*NN*RR];

// ---------------- K1: new usage + write content scores; zero d_out -----------
__global__ void k1_usage_sim(const float* __restrict__ memory,
                             const float* __restrict__ write_key,
                             const float* __restrict__ write_strength,
                             const float* __restrict__ free_gates,
                             const float* __restrict__ read_weightings,
                             const float* __restrict__ write_weighting,
                             const float* __restrict__ memory_usage,
                             float* __restrict__ out) {
    const int b   = blockIdx.y;
    const int tid = threadIdx.x;
    const int n   = blockIdx.x * 256 + tid;
    __shared__ float wk_s[WW];
    __shared__ float fg_s[RR];
    __shared__ float wkn;
    if (tid < WW) wk_s[tid] = write_key[b*WW + tid];
    if (tid < RR) fg_s[tid] = free_gates[b*RR + tid];
    if (blockIdx.y == 0 && blockIdx.x < 8) out[blockIdx.x*256 + tid] = 0.0f;
    __syncthreads();
    if (tid == 0) {
        float s = 0.f;
        for (int w = 0; w < WW; w++) s += wk_s[w]*wk_s[w];
        wkn = sqrtf(s);
    }
    __syncthreads();

    const size_t bn = (size_t)b*NN + n;
    float u  = memory_usage[bn];
    float wv = write_weighting[bn];
    float uw = u + wv - u*wv;
    float4 rw = *(const float4*)(read_weightings + bn*RR);
    float prod = (1.f - rw.x*fg_s[0]) * (1.f - rw.y*fg_s[1])
               * (1.f - rw.z*fg_s[2]) * (1.f - rw.w*fg_s[3]);
    g_usage[bn] = uw * prod;

    const float4* mrow = (const float4*)(memory + bn*WW);
    float dot = 0.f, nrm = 0.f;
    #pragma unroll
    for (int i = 0; i < 16; i++) {
        float4 m = mrow[i];
        dot += m.x*wk_s[i*4+0] + m.y*wk_s[i*4+1] + m.z*wk_s[i*4+2] + m.w*wk_s[i*4+3];
        nrm += m.x*m.x + m.y*m.y + m.z*m.z + m.w*m.w;
    }
    float sim = dot / (wkn * sqrtf(nrm) + EPSC);
    g_zw[bn] = write_strength[b] * sim;
}

// ---------------- K2: per-batch sort -> allocation weights (1024 thr) --------
__global__ void k2_alloc() {
    const int b   = blockIdx.x;
    const int tid = threadIdx.x;  // 1024 threads
    __shared__ float sv[NN];
    __shared__ int   si[NN];
    __shared__ float cp[1024];

    for (int i = tid; i < NN; i += 1024) { sv[i] = g_usage[(size_t)b*NN + i]; si[i] = i; }
    __syncthreads();

    for (int k = 2; k <= NN; k <<= 1) {
        for (int j = k >> 1; j > 0; j >>= 1) {
            for (int i = tid; i < NN; i += 1024) {
                int ixj = i ^ j;
                if (ixj > i) {
                    bool up = ((i & k) == 0);
                    float a = sv[i], c = sv[ixj];
                    bool sw = up ? (a > c) : (a < c);
                    if (sw) {
                        sv[i] = c; sv[ixj] = a;
                        int t = si[i]; si[i] = si[ixj]; si[ixj] = t;
                    }
                }
            }
            __syncthreads();
        }
    }

    float p = 1.f;
    const int base = tid * 4;
    #pragma unroll
    for (int t = 0; t < 4; t++) p *= sv[base + t];
    cp[tid] = p;
    __syncthreads();
    for (int off = 1; off < 1024; off <<= 1) {
        float v = cp[tid];
        float o = (tid >= off) ? cp[tid - off] : 1.f;
        __syncthreads();
        cp[tid] = v * o;
        __syncthreads();
    }
    float run = (tid == 0) ? 1.f : cp[tid - 1];
    #pragma unroll
    for (int t = 0; t < 4; t++) {
        float v = sv[base + t];
        g_alloc[(size_t)b*NN + si[base + t]] = (1.f - v) * run;
        run *= v;
    }
}

// ---------------- K3: softmax(cbw) + final ww; also zero g_fwd/g_bwd ---------
__global__ void k3_ww(const float* __restrict__ allocation_gate,
                      const float* __restrict__ write_gate) {
    const int b   = blockIdx.x;
    const int tid = threadIdx.x;  // 1024
    __shared__ float sh[32];
    const size_t bo = (size_t)b*NN;

    {
        float4 z4 = make_float4(0.f, 0.f, 0.f, 0.f);
        float4* f4 = (float4*)(g_fwd + bo*RR);
        float4* b4 = (float4*)(g_bwd + bo*RR);
        #pragma unroll
        for (int i = 0; i < 4; i++) { f4[tid + i*1024] = z4; b4[tid + i*1024] = z4; }
    }

    float z[4];
    float lm = -3.4e38f;
    #pragma unroll
    for (int k = 0; k < 4; k++) { z[k] = g_zw[bo + tid + k*1024]; lm = fmaxf(lm, z[k]); }
    for (int o = 16; o; o >>= 1) lm = fmaxf(lm, __shfl_xor_sync(0xffffffffu, lm, o));
    if ((tid & 31) == 0) sh[tid >> 5] = lm;
    __syncthreads();
    if (tid < 32) {
        float v = sh[tid];
        for (int o = 16; o; o >>= 1) v = fmaxf(v, __shfl_xor_sync(0xffffffffu, v, o));
        if (tid == 0) sh[0] = v;
    }
    __syncthreads();
    const float bmax = sh[0];
    __syncthreads();

    float e[4], ls = 0.f;
    #pragma unroll
    for (int k = 0; k < 4; k++) { e[k] = expf(z[k] - bmax); ls += e[k]; }
    for (int o = 16; o; o >>= 1) ls += __shfl_xor_sync(0xffffffffu, ls, o);
    if ((tid & 31) == 0) sh[tid >> 5] = ls;
    __syncthreads();
    if (tid < 32) {
        float v = sh[tid];
        for (int o = 16; o; o >>= 1) v += __shfl_xor_sync(0xffffffffu, v, o);
        if (tid == 0) sh[0] = v;
    }
    __syncthreads();
    const float bsum = sh[0];

    const float ag = allocation_gate[b], wg = write_gate[b];
    #pragma unroll
    for (int k = 0; k < 4; k++) {
        size_t idx = bo + tid + k*1024;
        float cbw = e[k] / bsum;
        g_ww[idx] = wg * (ag * g_alloc[idx] + (1.f - ag) * cbw);
    }
}

// ---------------- K4: memory erase/write + read content scores --------------
__global__ void k4_memupdate(const float* __restrict__ memory,
                             const float* __restrict__ erase_vector,
                             const float* __restrict__ write_vector,
                             const float* __restrict__ read_keys,
                             const float* __restrict__ read_strengths) {
    const int b   = blockIdx.y;
    const int tid = threadIdx.x;
    const int n   = blockIdx.x * 256 + tid;
    __shared__ float rk_s[WW][RR];
    __shared__ float ev_s[WW], wv_s[WW];
    __shared__ float nrk_s[RR], rs_s[RR];

    if (tid < WW) { ev_s[tid] = erase_vector[b*WW + tid]; wv_s[tid] = write_vector[b*WW + tid]; }
    { int w = tid >> 2, r = tid & 3; rk_s[w][r] = read_keys[b*WW*RR + tid]; }
    __syncthreads();
    if (tid < RR) {
        float s = 0.f;
        for (int w = 0; w < WW; w++) { float v = rk_s[w][tid]; s += v*v; }
        nrk_s[tid] = sqrtf(s);
        rs_s[tid]  = read_strengths[b*RR + tid];
    }
    __syncthreads();

    const size_t bn = (size_t)b*NN + n;
    const float wwn = g_ww[bn];
    const float4* mrow = (const float4*)(memory + bn*WW);
    float4* orow = (float4*)(g_memnew + bn*WW);

    float nrm = 0.f, s0 = 0.f, s1 = 0.f, s2 = 0.f, s3 = 0.f;
    #pragma unroll
    for (int i = 0; i < 16; i++) {
        float4 m = mrow[i];
        float mv[4] = {m.x, m.y, m.z, m.w};
        float ov[4];
        #pragma unroll
        for (int c = 0; c < 4; c++) {
            int w = i*4 + c;
            ov[c] = fmaf(mv[c], 1.f - wwn*ev_s[w], wwn*wv_s[w]);
            nrm += ov[c]*ov[c];
            s0 = fmaf(ov[c], rk_s[w][0], s0);
            s1 = fmaf(ov[c], rk_s[w][1], s1);
            s2 = fmaf(ov[c], rk_s[w][2], s2);
            s3 = fmaf(ov[c], rk_s[w][3], s3);
        }
        float4 o4 = make_float4(ov[0], ov[1], ov[2], ov[3]);
        orow[i] = o4;
    }
    const float nn = sqrtf(nrm);
    float4 zr;
    zr.x = rs_s[0]*s0 / (nn*nrk_s[0] + EPSC);
    zr.y = rs_s[1]*s1 / (nn*nrk_s[1] + EPSC);
    zr.z = rs_s[2]*s2 / (nn*nrk_s[2] + EPSC);
    zr.w = rs_s[3]*s3 / (nn*nrk_s[3] + EPSC);
    *(float4*)(g_zr + bn*RR) = zr;
}

// ---------------- K5: softmax(cbr) per (b,r) ---------------------------------
__global__ void k5_cbr() {
    const int r = blockIdx.x, b = blockIdx.y;
    const int tid = threadIdx.x;  // 256
    __shared__ float sh[8];
    const size_t bo = (size_t)b*NN;

    float z[16];
    float lm = -3.4e38f;
    #pragma unroll
    for (int k = 0; k < 16; k++) {
        size_t idx = (bo + tid + (size_t)k*256)*RR + r;
        z[k] = g_zr[idx];
        lm = fmaxf(lm, z[k]);
    }
    for (int o = 16; o; o >>= 1) lm = fmaxf(lm, __shfl_xor_sync(0xffffffffu, lm, o));
    if ((tid & 31) == 0) sh[tid >> 5] = lm;
    __syncthreads();
    if (tid < 8) {
        float v = sh[tid];
        for (int o = 4; o; o >>= 1) v = fmaxf(v, __shfl_xor_sync(0xffu, v, o));
        if (tid == 0) sh[0] = v;
    }
    __syncthreads();
    const float bmax = sh[0];
    __syncthreads();

    float ls = 0.f;
    #pragma unroll
    for (int k = 0; k < 16; k++) { z[k] = expf(z[k] - bmax); ls += z[k]; }
    for (int o = 16; o; o >>= 1) ls += __shfl_xor_sync(0xffffffffu, ls, o);
    if ((tid & 31) == 0) sh[tid >> 5] = ls;
    __syncthreads();
    if (tid < 8) {
        float v = sh[tid];
        for (int o = 4; o; o >>= 1) v += __shfl_xor_sync(0xffu, v, o);
        if (tid == 0) sh[0] = v;
    }
    __syncthreads();
    const float bsum = sh[0];

    #pragma unroll
    for (int k = 0; k < 16; k++) {
        size_t idx = (bo + tid + (size_t)k*256)*RR + r;
        g_cbr[idx] = z[k] / bsum;
    }
}

// ---------------- K6 v9: pre-packed smem operands ----------------------------
// a[n][m] = (1-ww_n-ww_m)*L[n][m] + ww_n*p_m  (diag corrected in K7)
// fwd[n,r] += a[n][m]*rwo[m,r]   ;   bwd[m,r] += a[n][m]*rwo[n,r]
// 2 cols/thread; row pairs packed into f32x2 (lo=even row, hi=odd row).
// Row-side operands staged in smem ALREADY PACKED -> no per-iter pack MOVs.
#define K6_TM   64    // cols per block (32 lanes x 2)
#define K6_ROWS 256   // rows per block (8 warps x 16 groups of 2)
__global__ void __launch_bounds__(256, 3) k6_link(const float* __restrict__ L,
                        const float* __restrict__ rwo,
                        const float* __restrict__ prec) {
    const int b    = blockIdx.z;
    const int m0   = blockIdx.x * K6_TM;
    const int n00  = blockIdx.y * K6_ROWS;
    const int tid  = threadIdx.x;     // 256
    const int warp = tid >> 5, lane = tid & 31;
    const size_t bo = (size_t)b * NN;
    const int mc   = m0 + lane * 2;   // this thread's 2 columns

    __shared__ __align__(16) u64 rnp_s[K6_ROWS/2][4];  // packed rn by row pair
    __shared__ __align__(16) u64 aw_s[K6_ROWS/2];      // packed (1-w0, 1-w1)
    __shared__ __align__(16) u64 wp_s[K6_ROWS/2];      // packed (w0, w1)
    __shared__ __align__(16) float bw_s[8][K6_TM][4];  // per-warp bwd slabs

    // stage ALL row operands once, pre-packed (one barrier for the mainloop)
    if (tid < K6_ROWS/2) {
        const size_t r0 = bo + n00 + tid*2;
        const float w0 = g_ww[r0], w1 = g_ww[r0 + 1];
        aw_s[tid] = pack2(1.f - w0, 1.f - w1);
        wp_s[tid] = pack2(w0, w1);
        const float4 rA = *(const float4*)(rwo + r0*4);
        const float4 rB = *(const float4*)(rwo + (r0 + 1)*4);
        rnp_s[tid][0] = pack2(rA.x, rB.x);
        rnp_s[tid][1] = pack2(rA.y, rB.y);
        rnp_s[tid][2] = pack2(rA.z, rB.z);
        rnp_s[tid][3] = pack2(rA.w, rB.w);
    }

    // per-thread column constants (dup-packed)
    const float2 wmv = *(const float2*)(g_ww + bo + mc);
    const float2 pmv = *(const float2*)(prec + bo + mc);
    const u64 negwm_d[2] = { pack2(-wmv.x, -wmv.x), pack2(-wmv.y, -wmv.y) };
    const u64 pm_d[2]    = { pack2(pmv.x, pmv.x),   pack2(pmv.y, pmv.y) };
    const float4 rm0 = __ldg((const float4*)(rwo + (size_t)(bo + mc + 0)*4));
    const float4 rm1 = __ldg((const float4*)(rwo + (size_t)(bo + mc + 1)*4));
    u64 rm_d[2][4];
    rm_d[0][0] = pack2(rm0.x, rm0.x); rm_d[0][1] = pack2(rm0.y, rm0.y);
    rm_d[0][2] = pack2(rm0.z, rm0.z); rm_d[0][3] = pack2(rm0.w, rm0.w);
    rm_d[1][0] = pack2(rm1.x, rm1.x); rm_d[1][1] = pack2(rm1.y, rm1.y);
    rm_d[1][2] = pack2(rm1.z, rm1.z); rm_d[1][3] = pack2(rm1.w, rm1.w);

    u64 bacc_p[2][4];   // bwd partials [col][r]; lo=even-row sum, hi=odd-row sum
    #pragma unroll
    for (int c = 0; c < 2; c++)
        #pragma unroll
        for (int r = 0; r < 4; r++) bacc_p[c][r] = 0ull;

    __syncthreads();

    const float* Lb0 = L + (bo + n00) * (size_t)NN + mc;
    int rl = warp * 8;   // group 0's row within tile
    float2 c0 = __ldg((const float2*)(Lb0 + (size_t)rl * NN));
    float2 c1 = __ldg((const float2*)(Lb0 + (size_t)(rl + 1) * NN));

    #pragma unroll 4
    for (int it = 0; it < 16; it++) {
        // prefetch next group (clamped on last iter; redundant L1-hit load)
        const int itn = (it < 15) ? (it + 1) : 15;
        const int rln = ((itn >> 2) << 6) + warp * 8 + ((itn & 3) << 1);
        float2 p0 = __ldg((const float2*)(Lb0 + (size_t)rln * NN));
        float2 p1 = __ldg((const float2*)(Lb0 + (size_t)(rln + 1) * NN));

        // compute current group (rows rl, rl+1) — operands pre-packed in smem
        const int ip = rl >> 1;
        const u64 AA  = aw_s[ip];
        const u64 WWp = wp_s[ip];
        const u64 rn_p0 = rnp_s[ip][0];
        const u64 rn_p1 = rnp_s[ip][1];
        const u64 rn_p2 = rnp_s[ip][2];
        const u64 rn_p3 = rnp_s[ip][3];
        u64 lv_p[2];
        lv_p[0] = pack2(c0.x, c1.x);
        lv_p[1] = pack2(c0.y, c1.y);

        u64 v_p[4];   // fwd partials per r: (row_even, row_odd)
        {
            const u64 aw0 = add2(AA, negwm_d[0]);
            const u64 t0  = mul2(WWp, pm_d[0]);
            const u64 ap0 = fma2(lv_p[0], aw0, t0);
            bacc_p[0][0] = fma2(ap0, rn_p0, bacc_p[0][0]);
            bacc_p[0][1] = fma2(ap0, rn_p1, bacc_p[0][1]);
            bacc_p[0][2] = fma2(ap0, rn_p2, bacc_p[0][2]);
            bacc_p[0][3] = fma2(ap0, rn_p3, bacc_p[0][3]);
            v_p[0] = mul2(ap0, rm_d[0][0]);
            v_p[1] = mul2(ap0, rm_d[0][1]);
            v_p[2] = mul2(ap0, rm_d[0][2]);
            v_p[3] = mul2(ap0, rm_d[0][3]);
            const u64 aw1 = add2(AA, negwm_d[1]);
            const u64 t1  = mul2(WWp, pm_d[1]);
            const u64 ap1 = fma2(lv_p[1], aw1, t1);
            bacc_p[1][0] = fma2(ap1, rn_p0, bacc_p[1][0]);
            bacc_p[1][1] = fma2(ap1, rn_p1, bacc_p[1][1]);
            bacc_p[1][2] = fma2(ap1, rn_p2, bacc_p[1][2]);
            bacc_p[1][3] = fma2(ap1, rn_p3, bacc_p[1][3]);
            v_p[0] = fma2(ap1, rm_d[1][0], v_p[0]);
            v_p[1] = fma2(ap1, rm_d[1][1], v_p[1]);
            v_p[2] = fma2(ap1, rm_d[1][2], v_p[2]);
            v_p[3] = fma2(ap1, rm_d[1][3], v_p[3]);
        }

        // packed reduce-scatter: 4 u64 items over 32 lanes
        {
            bool up;
            up = (lane & 16) != 0;
            #pragma unroll
            for (int i = 0; i < 2; i++) {
                u64 send = up ? v_p[i] : v_p[i+2];
                u64 recv = __shfl_xor_sync(0xffffffffu, send, 16);
                v_p[i] = add2(up ? v_p[i+2] : v_p[i], recv);
            }
            up = (lane & 8) != 0;
            {
                u64 send = up ? v_p[0] : v_p[1];
                u64 recv = __shfl_xor_sync(0xffffffffu, send, 8);
                v_p[0] = add2(up ? v_p[1] : v_p[0], recv);
            }
            v_p[0] = add2(v_p[0], __shfl_xor_sync(0xffffffffu, v_p[0], 4));
            v_p[0] = add2(v_p[0], __shfl_xor_sync(0xffffffffu, v_p[0], 2));
            v_p[0] = add2(v_p[0], __shfl_xor_sync(0xffffffffu, v_p[0], 1));
        }
        // lane holds item j = 2*bit4 + bit3 = r ; writers: lane%8 == 0
        if ((lane & 7) == 0) {
            const int r = (((lane >> 4) & 1) << 1) | ((lane >> 3) & 1);
            float lo, hi;
            unpack2(lo, hi, v_p[0]);
            const size_t rowb = bo + n00 + rl;
            atomicAdd(g_fwd + rowb*4 + r,       lo);
            atomicAdd(g_fwd + (rowb + 1)*4 + r, hi);
        }

        c0 = p0; c1 = p1; rl = rln;
    }

    // bwd merge: unpack (even+odd halves), per-warp smem slabs, tree add + RED
    __syncthreads();
    {
        float b0[4], b1[4];
        #pragma unroll
        for (int r = 0; r < 4; r++) {
            float lo, hi;
            unpack2(lo, hi, bacc_p[0][r]); b0[r] = lo + hi;
            unpack2(lo, hi, bacc_p[1][r]); b1[r] = lo + hi;
        }
        *(float4*)&bw_s[warp][lane*2 + 0][0] = make_float4(b0[0], b0[1], b0[2], b0[3]);
        *(float4*)&bw_s[warp][lane*2 + 1][0] = make_float4(b1[0], b1[1], b1[2], b1[3]);
    }
    __syncthreads();
    {
        const int col = tid >> 2, r = tid & 3;   // 256 threads = 64 cols x 4 r
        float s = bw_s[0][col][r] + bw_s[1][col][r] + bw_s[2][col][r] + bw_s[3][col][r]
                + bw_s[4][col][r] + bw_s[5][col][r] + bw_s[6][col][r] + bw_s[7][col][r];
        atomicAdd(g_bwd + (size_t)(bo + m0 + col)*4 + r, s);
    }
}

// ---------------- K7: combine read modes (+ diag correction) + bwr -----------
__global__ void k7_read(const float* __restrict__ read_modes,
                        const float* __restrict__ L,
                        const float* __restrict__ prec,
                        const float* __restrict__ rwo,
                        float* __restrict__ out) {
    const int b   = blockIdx.y;
    const int n0  = blockIdx.x * 256;
    const int tid = threadIdx.x;          // 256
    const int w = tid & 63, r = tid >> 6;
    const size_t bo = (size_t)b * NN;
    __shared__ float rw_s[64][4];
    const int nl = tid >> 2, rr = tid & 3;
    const float mm0 = read_modes[b*12 + rr];
    const float mm1 = read_modes[b*12 + 4 + rr];
    const float mm2 = read_modes[b*12 + 8 + rr];

    float acc = 0.f;
    for (int c = 0; c < 256; c += 64) {
        const int n = n0 + c + nl;
        size_t idx = (bo + n)*4 + rr;
        // diag correction: a_nn = (1-2ww_n)L[n,n] + ww_n p_n ; subtract a_nn*rwo[n,r]
        const float Lnn = L[(bo + n)*(size_t)NN + n];
        const float wwn = g_ww[bo + n];
        const float ann = fmaf(1.f - 2.f*wwn, Lnn, wwn * prec[bo + n]);
        const float corr = ann * rwo[idx];
        float rwv = mm0*(g_bwd[idx] - corr) + mm1*g_cbr[idx] + mm2*(g_fwd[idx] - corr);
        __syncthreads();
        rw_s[nl][rr] = rwv;
        __syncthreads();
        const float* mp = g_memnew + (bo + n0 + c)*WW + w;
        #pragma unroll 8
        for (int q = 0; q < 64; q++)
            acc = fmaf(mp[(size_t)q*WW], rw_s[q][r], acc);
    }
    atomicAdd(&out[b*WW*RR + w*RR + r], acc);
}

// ---------------- launch -----------------------------------------------------
extern "C" void kernel_launch(void* const* d_in, const int* in_sizes, int n_in,
                              void* d_out, int out_size) {
    const float* erase_vector    = (const float*)d_in[0];
    const float* free_gates      = (const float*)d_in[1];
    const float* allocation_gate = (const float*)d_in[2];
    const float* write_gate      = (const float*)d_in[3];
    const float* read_modes      = (const float*)d_in[4];
    const float* read_strengths  = (const float*)d_in[5];
    const float* read_keys       = (const float*)d_in[6];
    const float* write_vector    = (const float*)d_in[7];
    const float* write_key       = (const float*)d_in[8];
    const float* write_strength  = (const float*)d_in[9];
    const float* memory          = (const float*)d_in[10];
    const float* read_weightings = (const float*)d_in[11];
    const float* write_weighting = (const float*)d_in[12];
    const float* memory_usage    = (const float*)d_in[13];
    const float* link_matrix     = (const float*)d_in[14];
    const float* precedence      = (const float*)d_in[15];
    float* out = (float*)d_out;

    k1_usage_sim<<<dim3(16, 8), 256>>>(memory, write_key, write_strength, free_gates,
                                       read_weightings, write_weighting, memory_usage, out);
    k2_alloc<<<8, 1024>>>();
    k3_ww<<<8, 1024>>>(allocation_gate, write_gate);
    // k6 at launch index 3 so ncu's fixed-skip capture lands on it
    k6_link<<<dim3(NN/K6_TM, NN/K6_ROWS, BB), 256>>>(link_matrix, read_weightings, precedence);
    k4_memupdate<<<dim3(16, 8), 256>>>(memory, erase_vector, write_vector,
                                       read_keys, read_strengths);
    k5_cbr<<<dim3(4, 8), 256>>>();
    k7_read<<<dim3(16, 8), 256>>>(read_modes, link_matrix, precedence, read_weightings, out);
}

// round 16
// speedup vs baseline: 1.0302x; 1.0302x over previous
#include <cuda_runtime.h>
#include <math.h>

#define BB 8
#define NN 4096
#define WW 64
#define RR 4
#define EPSC 1e-8f

typedef unsigned long long u64;

// ---- f32x2 packed helpers (sm_103a) -----------------------------------------
__device__ __forceinline__ u64 pack2(float lo, float hi) {
    u64 r; asm("mov.b64 %0, {%1, %2};" : "=l"(r) : "f"(lo), "f"(hi)); return r;
}
__device__ __forceinline__ void unpack2(float& lo, float& hi, u64 v) {
    asm("mov.b64 {%0, %1}, %2;" : "=f"(lo), "=f"(hi) : "l"(v));
}
__device__ __forceinline__ u64 fma2(u64 a, u64 b, u64 c) {
    u64 d; asm("fma.rn.f32x2 %0, %1, %2, %3;" : "=l"(d) : "l"(a), "l"(b), "l"(c)); return d;
}
__device__ __forceinline__ u64 add2(u64 a, u64 b) {
    u64 d; asm("add.rn.f32x2 %0, %1, %2;" : "=l"(d) : "l"(a), "l"(b)); return d;
}
__device__ __forceinline__ u64 mul2(u64 a, u64 b) {
    u64 d; asm("mul.rn.f32x2 %0, %1, %2;" : "=l"(d) : "l"(a), "l"(b)); return d;
}

// ---------------- scratch (no allocs allowed -> __device__ globals) ----------
__device__ __align__(16) float g_usage[BB*NN];
__device__ __align__(16) float g_zw[BB*NN];
__device__ __align__(16) float g_alloc[BB*NN];
__device__ __align__(16) float g_ww[BB*NN];
__device__ __align__(16) float g_memnew[BB*NN*WW];
__device__ __align__(16) float g_zr[BB*NN*RR];
__device__ __align__(16) float g_cbr[BB*NN*RR];
__device__ __align__(16) float g_fwd[BB*NN*RR];
__device__ __align__(16) float g_bwd[BB*NN*RR];

// ---------------- K1 v2: coalesced (warp = 4 rows); usage + zw; zero d_out ---
__global__ void k1_usage_sim(const float* __restrict__ memory,
                             const float* __restrict__ write_key,
                             const float* __restrict__ write_strength,
                             const float* __restrict__ free_gates,
                             const float* __restrict__ read_weightings,
                             const float* __restrict__ write_weighting,
                             const float* __restrict__ memory_usage,
                             float* __restrict__ out) {
    const int b    = blockIdx.y;
    const int tid  = threadIdx.x;   // 256
    const int warp = tid >> 5, lane = tid & 31;
    const int sub  = lane >> 3, cl = lane & 7;
    __shared__ float wk_s[WW];
    __shared__ float fg_s[RR];
    __shared__ float wkn;
    if (tid < WW) wk_s[tid] = write_key[b*WW + tid];
    if (tid < RR) fg_s[tid] = free_gates[b*RR + tid];
    if (blockIdx.y == 0 && blockIdx.x < 8) out[blockIdx.x*256 + tid] = 0.0f;
    __syncthreads();
    if (tid == 0) {
        float s = 0.f;
        for (int w = 0; w < WW; w++) s += wk_s[w]*wk_s[w];
        wkn = sqrtf(s);
    }
    __syncthreads();

    const int row = blockIdx.x * 32 + warp * 4 + sub;
    const size_t bn = (size_t)b*NN + row;

    float dot = 0.f, nrm = 0.f;
    #pragma unroll
    for (int p = 0; p < 2; p++) {
        const int c0 = p*32 + cl*4;
        const float4 m = *(const float4*)(memory + bn*WW + c0);
        dot += m.x*wk_s[c0+0] + m.y*wk_s[c0+1] + m.z*wk_s[c0+2] + m.w*wk_s[c0+3];
        nrm += m.x*m.x + m.y*m.y + m.z*m.z + m.w*m.w;
    }
    #pragma unroll
    for (int h = 4; h >= 1; h >>= 1) {
        dot += __shfl_xor_sync(0xffffffffu, dot, h);
        nrm += __shfl_xor_sync(0xffffffffu, nrm, h);
    }
    if (cl == 0) {
        const float sim = dot / (wkn * sqrtf(nrm) + EPSC);
        g_zw[bn] = write_strength[b] * sim;
        // usage update for this row
        const float u  = memory_usage[bn];
        const float wv = write_weighting[bn];
        const float uw = u + wv - u*wv;
        const float4 rw = *(const float4*)(read_weightings + bn*RR);
        const float prod = (1.f - rw.x*fg_s[0]) * (1.f - rw.y*fg_s[1])
                         * (1.f - rw.z*fg_s[2]) * (1.f - rw.w*fg_s[3]);
        g_usage[bn] = uw * prod;
    }
}

// ---------------- K2: per-batch sort -> allocation weights (1024 thr) --------
__global__ void k2_alloc() {
    const int b   = blockIdx.x;
    const int tid = threadIdx.x;  // 1024 threads
    __shared__ float sv[NN];
    __shared__ int   si[NN];
    __shared__ float cp[1024];

    for (int i = tid; i < NN; i += 1024) { sv[i] = g_usage[(size_t)b*NN + i]; si[i] = i; }
    __syncthreads();

    for (int k = 2; k <= NN; k <<= 1) {
        for (int j = k >> 1; j > 0; j >>= 1) {
            for (int i = tid; i < NN; i += 1024) {
                int ixj = i ^ j;
                if (ixj > i) {
                    bool up = ((i & k) == 0);
                    float a = sv[i], c = sv[ixj];
                    bool sw = up ? (a > c) : (a < c);
                    if (sw) {
                        sv[i] = c; sv[ixj] = a;
                        int t = si[i]; si[i] = si[ixj]; si[ixj] = t;
                    }
                }
            }
            __syncthreads();
        }
    }

    float p = 1.f;
    const int base = tid * 4;
    #pragma unroll
    for (int t = 0; t < 4; t++) p *= sv[base + t];
    cp[tid] = p;
    __syncthreads();
    for (int off = 1; off < 1024; off <<= 1) {
        float v = cp[tid];
        float o = (tid >= off) ? cp[tid - off] : 1.f;
        __syncthreads();
        cp[tid] = v * o;
        __syncthreads();
    }
    float run = (tid == 0) ? 1.f : cp[tid - 1];
    #pragma unroll
    for (int t = 0; t < 4; t++) {
        float v = sv[base + t];
        g_alloc[(size_t)b*NN + si[base + t]] = (1.f - v) * run;
        run *= v;
    }
}

// ---------------- K3: softmax(cbw) + final ww; also zero g_fwd/g_bwd ---------
__global__ void k3_ww(const float* __restrict__ allocation_gate,
                      const float* __restrict__ write_gate) {
    const int b   = blockIdx.x;
    const int tid = threadIdx.x;  // 1024
    __shared__ float sh[32];
    const size_t bo = (size_t)b*NN;

    {
        float4 z4 = make_float4(0.f, 0.f, 0.f, 0.f);
        float4* f4 = (float4*)(g_fwd + bo*RR);
        float4* b4 = (float4*)(g_bwd + bo*RR);
        #pragma unroll
        for (int i = 0; i < 4; i++) { f4[tid + i*1024] = z4; b4[tid + i*1024] = z4; }
    }

    float z[4];
    float lm = -3.4e38f;
    #pragma unroll
    for (int k = 0; k < 4; k++) { z[k] = g_zw[bo + tid + k*1024]; lm = fmaxf(lm, z[k]); }
    for (int o = 16; o; o >>= 1) lm = fmaxf(lm, __shfl_xor_sync(0xffffffffu, lm, o));
    if ((tid & 31) == 0) sh[tid >> 5] = lm;
    __syncthreads();
    if (tid < 32) {
        float v = sh[tid];
        for (int o = 16; o; o >>= 1) v = fmaxf(v, __shfl_xor_sync(0xffffffffu, v, o));
        if (tid == 0) sh[0] = v;
    }
    __syncthreads();
    const float bmax = sh[0];
    __syncthreads();

    float e[4], ls = 0.f;
    #pragma unroll
    for (int k = 0; k < 4; k++) { e[k] = expf(z[k] - bmax); ls += e[k]; }
    for (int o = 16; o; o >>= 1) ls += __shfl_xor_sync(0xffffffffu, ls, o);
    if ((tid & 31) == 0) sh[tid >> 5] = ls;
    __syncthreads();
    if (tid < 32) {
        float v = sh[tid];
        for (int o = 16; o; o >>= 1) v += __shfl_xor_sync(0xffffffffu, v, o);
        if (tid == 0) sh[0] = v;
    }
    __syncthreads();
    const float bsum = sh[0];

    const float ag = allocation_gate[b], wg = write_gate[b];
    #pragma unroll
    for (int k = 0; k < 4; k++) {
        size_t idx = bo + tid + k*1024;
        float cbw = e[k] / bsum;
        g_ww[idx] = wg * (ag * g_alloc[idx] + (1.f - ag) * cbw);
    }
}

// ---------------- K4 v2: coalesced (warp = 4 rows) mem update + zr -----------
__global__ void k4_memupdate(const float* __restrict__ memory,
                             const float* __restrict__ erase_vector,
                             const float* __restrict__ write_vector,
                             const float* __restrict__ read_keys,
                             const float* __restrict__ read_strengths) {
    const int b    = blockIdx.y;
    const int tid  = threadIdx.x;   // 256
    const int warp = tid >> 5, lane = tid & 31;
    const int sub  = lane >> 3, cl = lane & 7;
    __shared__ __align__(16) float4 rk_s[WW];   // rk[col] over r
    __shared__ float ev_s[WW], wv_s[WW];
    __shared__ float nrk_s[RR], rs_s[RR];

    if (tid < WW) { ev_s[tid] = erase_vector[b*WW + tid]; wv_s[tid] = write_vector[b*WW + tid]; }
    { int w = tid >> 2, r = tid & 3; ((float*)&rk_s[w])[r] = read_keys[b*WW*RR + tid]; }
    __syncthreads();
    if (tid < RR) {
        float s = 0.f;
        for (int w = 0; w < WW; w++) { float v = ((const float*)&rk_s[w])[tid]; s += v*v; }
        nrk_s[tid] = sqrtf(s);
        rs_s[tid]  = read_strengths[b*RR + tid];
    }
    __syncthreads();

    const int row = blockIdx.x * 32 + warp * 4 + sub;
    const size_t bn = (size_t)b*NN + row;
    const float wwn = g_ww[bn];

    float nrm = 0.f, s0 = 0.f, s1 = 0.f, s2 = 0.f, s3 = 0.f;
    #pragma unroll
    for (int p = 0; p < 2; p++) {
        const int c0 = p*32 + cl*4;
        const float4 m = *(const float4*)(memory + bn*WW + c0);
        const float mv[4] = {m.x, m.y, m.z, m.w};
        float ov[4];
        #pragma unroll
        for (int c = 0; c < 4; c++) {
            const int col = c0 + c;
            ov[c] = fmaf(mv[c], 1.f - wwn*ev_s[col], wwn*wv_s[col]);
            nrm += ov[c]*ov[c];
            const float4 rk = rk_s[col];
            s0 = fmaf(ov[c], rk.x, s0);
            s1 = fmaf(ov[c], rk.y, s1);
            s2 = fmaf(ov[c], rk.z, s2);
            s3 = fmaf(ov[c], rk.w, s3);
        }
        *(float4*)(g_memnew + bn*WW + c0) = make_float4(ov[0], ov[1], ov[2], ov[3]);
    }
    #pragma unroll
    for (int h = 4; h >= 1; h >>= 1) {
        nrm += __shfl_xor_sync(0xffffffffu, nrm, h);
        s0  += __shfl_xor_sync(0xffffffffu, s0, h);
        s1  += __shfl_xor_sync(0xffffffffu, s1, h);
        s2  += __shfl_xor_sync(0xffffffffu, s2, h);
        s3  += __shfl_xor_sync(0xffffffffu, s3, h);
    }
    if (cl == 0) {
        const float nn = sqrtf(nrm);
        float4 zr;
        zr.x = rs_s[0]*s0 / (nn*nrk_s[0] + EPSC);
        zr.y = rs_s[1]*s1 / (nn*nrk_s[1] + EPSC);
        zr.z = rs_s[2]*s2 / (nn*nrk_s[2] + EPSC);
        zr.w = rs_s[3]*s3 / (nn*nrk_s[3] + EPSC);
        *(float4*)(g_zr + bn*RR) = zr;
    }
}

// ---------------- K5: softmax(cbr) per (b,r) ---------------------------------
__global__ void k5_cbr() {
    const int r = blockIdx.x, b = blockIdx.y;
    const int tid = threadIdx.x;  // 256
    __shared__ float sh[8];
    const size_t bo = (size_t)b*NN;

    float z[16];
    float lm = -3.4e38f;
    #pragma unroll
    for (int k = 0; k < 16; k++) {
        size_t idx = (bo + tid + (size_t)k*256)*RR + r;
        z[k] = g_zr[idx];
        lm = fmaxf(lm, z[k]);
    }
    for (int o = 16; o; o >>= 1) lm = fmaxf(lm, __shfl_xor_sync(0xffffffffu, lm, o));
    if ((tid & 31) == 0) sh[tid >> 5] = lm;
    __syncthreads();
    if (tid < 8) {
        float v = sh[tid];
        for (int o = 4; o; o >>= 1) v = fmaxf(v, __shfl_xor_sync(0xffu, v, o));
        if (tid == 0) sh[0] = v;
    }
    __syncthreads();
    const float bmax = sh[0];
    __syncthreads();

    float ls = 0.f;
    #pragma unroll
    for (int k = 0; k < 16; k++) { z[k] = expf(z[k] - bmax); ls += z[k]; }
    for (int o = 16; o; o >>= 1) ls += __shfl_xor_sync(0xffffffffu, ls, o);
    if ((tid & 31) == 0) sh[tid >> 5] = ls;
    __syncthreads();
    if (tid < 8) {
        float v = sh[tid];
        for (int o = 4; o; o >>= 1) v += __shfl_xor_sync(0xffu, v, o);
        if (tid == 0) sh[0] = v;
    }
    __syncthreads();
    const float bsum = sh[0];

    #pragma unroll
    for (int k = 0; k < 16; k++) {
        size_t idx = (bo + tid + (size_t)k*256)*RR + r;
        g_cbr[idx] = z[k] / bsum;
    }
}

// ---------------- K6 v8 (reverted, best): prefetch-1, single-stage smem ------
// a[n][m] = (1-ww_n-ww_m)*L[n][m] + ww_n*p_m  (diag corrected in K7)
// fwd[n,r] += a[n][m]*rwo[m,r]   ;   bwd[m,r] += a[n][m]*rwo[n,r]
#define K6_TM   64    // cols per block (32 lanes x 2)
#define K6_ROWS 256   // rows per block (8 warps x 16 groups of 2)
__global__ void __launch_bounds__(256, 3) k6_link(const float* __restrict__ L,
                        const float* __restrict__ rwo,
                        const float* __restrict__ prec) {
    const int b    = blockIdx.z;
    const int m0   = blockIdx.x * K6_TM;
    const int n00  = blockIdx.y * K6_ROWS;
    const int tid  = threadIdx.x;     // 256
    const int warp = tid >> 5, lane = tid & 31;
    const size_t bo = (size_t)b * NN;
    const int mc   = m0 + lane * 2;   // this thread's 2 columns

    __shared__ float wwn_s[K6_ROWS];
    __shared__ __align__(16) float4 rn_s[K6_ROWS];
    __shared__ __align__(16) float bw_s[8][K6_TM][4];   // per-warp bwd slabs

    // stage ALL rows once (one barrier for the whole mainloop)
    wwn_s[tid] = g_ww[bo + n00 + tid];
    rn_s[tid]  = *(const float4*)(rwo + (size_t)(bo + n00 + tid)*4);

    // per-thread column constants (dup-packed)
    const float2 wmv = *(const float2*)(g_ww + bo + mc);
    const float2 pmv = *(const float2*)(prec + bo + mc);
    const u64 negwm_d[2] = { pack2(-wmv.x, -wmv.x), pack2(-wmv.y, -wmv.y) };
    const u64 pm_d[2]    = { pack2(pmv.x, pmv.x),   pack2(pmv.y, pmv.y) };
    const float4 rm0 = __ldg((const float4*)(rwo + (size_t)(bo + mc + 0)*4));
    const float4 rm1 = __ldg((const float4*)(rwo + (size_t)(bo + mc + 1)*4));
    u64 rm_d[2][4];
    rm_d[0][0] = pack2(rm0.x, rm0.x); rm_d[0][1] = pack2(rm0.y, rm0.y);
    rm_d[0][2] = pack2(rm0.z, rm0.z); rm_d[0][3] = pack2(rm0.w, rm0.w);
    rm_d[1][0] = pack2(rm1.x, rm1.x); rm_d[1][1] = pack2(rm1.y, rm1.y);
    rm_d[1][2] = pack2(rm1.z, rm1.z); rm_d[1][3] = pack2(rm1.w, rm1.w);

    u64 bacc_p[2][4];   // bwd partials [col][r]; lo=even-row sum, hi=odd-row sum
    #pragma unroll
    for (int c = 0; c < 2; c++)
        #pragma unroll
        for (int r = 0; r < 4; r++) bacc_p[c][r] = 0ull;

    __syncthreads();

    const float* Lb0 = L + (bo + n00) * (size_t)NN + mc;
    int rl = warp * 8;   // group 0's row within tile
    float2 c0 = __ldg((const float2*)(Lb0 + (size_t)rl * NN));
    float2 c1 = __ldg((const float2*)(Lb0 + (size_t)(rl + 1) * NN));

    #pragma unroll 4
    for (int it = 0; it < 16; it++) {
        // prefetch next group (clamped on last iter; redundant L1-hit load)
        const int itn = (it < 15) ? (it + 1) : 15;
        const int rln = ((itn >> 2) << 6) + warp * 8 + ((itn & 3) << 1);
        float2 p0 = __ldg((const float2*)(Lb0 + (size_t)rln * NN));
        float2 p1 = __ldg((const float2*)(Lb0 + (size_t)(rln + 1) * NN));

        // compute current group (rows rl, rl+1)
        const float w0 = wwn_s[rl], w1 = wwn_s[rl + 1];
        const u64 AA  = pack2(1.f - w0, 1.f - w1);
        const u64 WWp = pack2(w0, w1);
        const float4 rnA = rn_s[rl];
        const float4 rnB = rn_s[rl + 1];
        u64 rn_p[4];
        rn_p[0] = pack2(rnA.x, rnB.x); rn_p[1] = pack2(rnA.y, rnB.y);
        rn_p[2] = pack2(rnA.z, rnB.z); rn_p[3] = pack2(rnA.w, rnB.w);
        u64 lv_p[2];
        lv_p[0] = pack2(c0.x, c1.x);
        lv_p[1] = pack2(c0.y, c1.y);

        u64 v_p[4];   // fwd partials per r: (row_even, row_odd)
        {
            const u64 aw0 = add2(AA, negwm_d[0]);
            const u64 t0  = mul2(WWp, pm_d[0]);
            const u64 ap0 = fma2(lv_p[0], aw0, t0);
            #pragma unroll
            for (int r = 0; r < 4; r++) {
                bacc_p[0][r] = fma2(ap0, rn_p[r], bacc_p[0][r]);
                v_p[r] = mul2(ap0, rm_d[0][r]);
            }
            const u64 aw1 = add2(AA, negwm_d[1]);
            const u64 t1  = mul2(WWp, pm_d[1]);
            const u64 ap1 = fma2(lv_p[1], aw1, t1);
            #pragma unroll
            for (int r = 0; r < 4; r++) {
                bacc_p[1][r] = fma2(ap1, rn_p[r], bacc_p[1][r]);
                v_p[r] = fma2(ap1, rm_d[1][r], v_p[r]);
            }
        }

        // packed reduce-scatter: 4 u64 items over 32 lanes
        {
            bool up;
            up = (lane & 16) != 0;
            #pragma unroll
            for (int i = 0; i < 2; i++) {
                u64 send = up ? v_p[i] : v_p[i+2];
                u64 recv = __shfl_xor_sync(0xffffffffu, send, 16);
                v_p[i] = add2(up ? v_p[i+2] : v_p[i], recv);
            }
            up = (lane & 8) != 0;
            {
                u64 send = up ? v_p[0] : v_p[1];
                u64 recv = __shfl_xor_sync(0xffffffffu, send, 8);
                v_p[0] = add2(up ? v_p[1] : v_p[0], recv);
            }
            v_p[0] = add2(v_p[0], __shfl_xor_sync(0xffffffffu, v_p[0], 4));
            v_p[0] = add2(v_p[0], __shfl_xor_sync(0xffffffffu, v_p[0], 2));
            v_p[0] = add2(v_p[0], __shfl_xor_sync(0xffffffffu, v_p[0], 1));
        }
        // lane holds item j = 2*bit4 + bit3 = r ; writers: lane%8 == 0
        if ((lane & 7) == 0) {
            const int r = (((lane >> 4) & 1) << 1) | ((lane >> 3) & 1);
            float lo, hi;
            unpack2(lo, hi, v_p[0]);
            const size_t rowb = bo + n00 + rl;
            atomicAdd(g_fwd + rowb*4 + r,       lo);
            atomicAdd(g_fwd + (rowb + 1)*4 + r, hi);
        }

        c0 = p0; c1 = p1; rl = rln;
    }

    // bwd merge: unpack (even+odd halves), per-warp smem slabs, tree add + RED
    __syncthreads();
    {
        float b0[4], b1[4];
        #pragma unroll
        for (int r = 0; r < 4; r++) {
            float lo, hi;
            unpack2(lo, hi, bacc_p[0][r]); b0[r] = lo + hi;
            unpack2(lo, hi, bacc_p[1][r]); b1[r] = lo + hi;
        }
        *(float4*)&bw_s[warp][lane*2 + 0][0] = make_float4(b0[0], b0[1], b0[2], b0[3]);
        *(float4*)&bw_s[warp][lane*2 + 1][0] = make_float4(b1[0], b1[1], b1[2], b1[3]);
    }
    __syncthreads();
    {
        const int col = tid >> 2, r = tid & 3;   // 256 threads = 64 cols x 4 r
        float s = bw_s[0][col][r] + bw_s[1][col][r] + bw_s[2][col][r] + bw_s[3][col][r]
                + bw_s[4][col][r] + bw_s[5][col][r] + bw_s[6][col][r] + bw_s[7][col][r];
        atomicAdd(g_bwd + (size_t)(bo + m0 + col)*4 + r, s);
    }
}

// ---------------- K7: combine read modes (+ diag correction) + bwr -----------
__global__ void k7_read(const float* __restrict__ read_modes,
                        const float* __restrict__ L,
                        const float* __restrict__ prec,
                        const float* __restrict__ rwo,
                        float* __restrict__ out) {
    const int b   = blockIdx.y;
    const int n0  = blockIdx.x * 256;
    const int tid = threadIdx.x;          // 256
    const int w = tid & 63, r = tid >> 6;
    const size_t bo = (size_t)b * NN;
    __shared__ float rw_s[64][4];
    const int nl = tid >> 2, rr = tid & 3;
    const float mm0 = read_modes[b*12 + rr];
    const float mm1 = read_modes[b*12 + 4 + rr];
    const float mm2 = read_modes[b*12 + 8 + rr];

    float acc = 0.f;
    for (int c = 0; c < 256; c += 64) {
        const int n = n0 + c + nl;
        size_t idx = (bo + n)*4 + rr;
        // diag correction: a_nn = (1-2ww_n)L[n,n] + ww_n p_n ; subtract a_nn*rwo[n,r]
        const float Lnn = L[(bo + n)*(size_t)NN + n];
        const float wwn = g_ww[bo + n];
        const float ann = fmaf(1.f - 2.f*wwn, Lnn, wwn * prec[bo + n]);
        const float corr = ann * rwo[idx];
        float rwv = mm0*(g_bwd[idx] - corr) + mm1*g_cbr[idx] + mm2*(g_fwd[idx] - corr);
        __syncthreads();
        rw_s[nl][rr] = rwv;
        __syncthreads();
        const float* mp = g_memnew + (bo + n0 + c)*WW + w;
        #pragma unroll 8
        for (int q = 0; q < 64; q++)
            acc = fmaf(mp[(size_t)q*WW], rw_s[q][r], acc);
    }
    atomicAdd(&out[b*WW*RR + w*RR + r], acc);
}

// ---------------- launch -----------------------------------------------------
extern "C" void kernel_launch(void* const* d_in, const int* in_sizes, int n_in,
                              void* d_out, int out_size) {
    const float* erase_vector    = (const float*)d_in[0];
    const float* free_gates      = (const float*)d_in[1];
    const float* allocation_gate = (const float*)d_in[2];
    const float* write_gate      = (const float*)d_in[3];
    const float* read_modes      = (const float*)d_in[4];
    const float* read_strengths  = (const float*)d_in[5];
    const float* read_keys       = (const float*)d_in[6];
    const float* write_vector    = (const float*)d_in[7];
    const float* write_key       = (const float*)d_in[8];
    const float* write_strength  = (const float*)d_in[9];
    const float* memory          = (const float*)d_in[10];
    const float* read_weightings = (const float*)d_in[11];
    const float* write_weighting = (const float*)d_in[12];
    const float* memory_usage    = (const float*)d_in[13];
    const float* link_matrix     = (const float*)d_in[14];
    const float* precedence      = (const float*)d_in[15];
    float* out = (float*)d_out;

    k1_usage_sim<<<dim3(128, 8), 256>>>(memory, write_key, write_strength, free_gates,
                                        read_weightings, write_weighting, memory_usage, out);
    k2_alloc<<<8, 1024>>>();
    k3_ww<<<8, 1024>>>(allocation_gate, write_gate);
    // k6 at launch index 3 so ncu's fixed-skip capture lands on it
    k6_link<<<dim3(NN/K6_TM, NN/K6_ROWS, BB), 256>>>(link_matrix, read_weightings, precedence);
    k4_memupdate<<<dim3(128, 8), 256>>>(memory, erase_vector, write_vector,
                                        read_keys, read_strengths);
    k5_cbr<<<dim3(4, 8), 256>>>();
    k7_read<<<dim3(16, 8), 256>>>(read_modes, link_matrix, precedence, read_weightings, out);
}